// round 11
// baseline (speedup 1.0000x reference)
#include <cuda_runtime.h>
#include <cstdint>

// ---------------------------------------------------------------------------
// Seq2seq BiLSTM (encoder 336 steps + autoregressive decoder, 24 iters)
// Persistent cooperative kernel, packed fp32x2 FFMA2 GEMM, 256 thr/CTA.
//
// Grid = 128 CTAs = 2 dirs x 4 batch-tiles(32) x 16 j-tiles(16).
// Thread owns 2 batch rows x 4 gates of one hidden unit (f32x2 gate pairs):
//   acc[bi][0]=(g_i,g_f), acc[bi][1]=(g_g,g_o); W pair = one LDS.64.
// g_h is DOUBLE-BUFFERED by step parity (no read/write hazard across CTAs).
// Per step: PRE phase (x staging + x-part GEMM) before the flag wait.
// Group barrier = 16 CTAs sharing (dir,b-tile); projections use minimal
// producer-set waits. release-store/acquire-load flags, hard spin.
// ---------------------------------------------------------------------------

#define NBLK 128
#define NTHR 256

namespace {
constexpr int BATCH = 128;
constexpr int SEQLEN = 336;
constexpr int PRED = 24;
constexpr int IN = 64;
constexpr int HID = 256;
constexpr int KTOT = IN + HID;          // 320
constexpr int WS = 68;                  // W smem row stride (floats), 272B
constexpr int AS = 328;                 // A smem row stride (floats), 1312B
constexpr int SMEM_FLOATS = KTOT * WS + 32 * AS + 64 + NTHR;
constexpr int SMEM_BYTES = SMEM_FLOATS * 4;
}

__device__ float g_h[2][2 * BATCH * HID];       // [parity][dir*BATCH + b][HID]
__device__ float g_y[PRED * BATCH * IN];
__device__ int   g_flags[NBLK];

using u64 = unsigned long long;

__device__ __forceinline__ int ld_acq(const int* p) {
    int v;
    asm volatile("ld.global.acquire.gpu.b32 %0, [%1];" : "=r"(v) : "l"(p) : "memory");
    return v;
}
__device__ __forceinline__ void st_rel(int* p, int v) {
    asm volatile("st.global.release.gpu.b32 [%0], %1;" :: "l"(p), "r"(v) : "memory");
}

__device__ __forceinline__ u64 ffma2(u64 a, u64 b, u64 c) {
    u64 d;
    asm("fma.rn.f32x2 %0, %1, %2, %3;" : "=l"(d) : "l"(a), "l"(b), "l"(c));
    return d;
}
__device__ __forceinline__ u64 pack2(float lo, float hi) {
    u64 d;
    asm("mov.b64 %0, {%1, %2};" : "=l"(d) : "f"(lo), "f"(hi));
    return d;
}
__device__ __forceinline__ void unpack2(float& lo, float& hi, u64 v) {
    asm("mov.b64 {%0, %1}, %2;" : "=f"(lo), "=f"(hi) : "l"(v));
}

__device__ __forceinline__ float fsig(float x) {
    return __fdividef(1.0f, 1.0f + __expf(-x));
}
__device__ __forceinline__ float ftanh(float x) {
    float ax = fabsf(x);
    float t = __expf(-2.0f * ax);
    float r = __fdividef(1.0f - t, 1.0f + t);
    return copysignf(r, x);
}

__device__ __forceinline__ void release(int v) {
    __syncthreads();
    if (threadIdx.x == 0) st_rel(&g_flags[blockIdx.x], v);
}
__device__ __forceinline__ void waitf(int base, int cnt, int v) {
    if (threadIdx.x < cnt) {
        const int* p = &g_flags[base + threadIdx.x];
        while (ld_acq(p) < v) { }
    }
    __syncthreads();
}

// W slice -> SMEM: Wsm[k*WS + jj*4 + g], source row = g*256 + j0 + jj.
__device__ void load_phase_weights(float* Wsm, float* bsum,
                                   const float* __restrict__ Wih,
                                   const float* __restrict__ Whh,
                                   const float* __restrict__ bih,
                                   const float* __restrict__ bhh,
                                   int d, int j0) {
    for (int idx = threadIdx.x; idx < 64 * KTOT; idx += NTHR) {
        int c = idx / KTOT;
        int k = idx - c * KTOT;
        int jj = c >> 2, g = c & 3;
        int row = g * 256 + j0 + jj;
        float v = (k < IN) ? Wih[(d * 1024 + row) * IN + k]
                           : Whh[(d * 1024 + row) * HID + (k - IN)];
        Wsm[k * WS + c] = v;
    }
    for (int c = threadIdx.x; c < 64; c += NTHR) {
        int jj = c >> 2, g = c & 3;
        int row = g * 256 + j0 + jj;
        bsum[c] = bih[d * 1024 + row] + bhh[d * 1024 + row];
    }
}

// Packed f32x2 GEMM over k range [k0,k1): 2 batch rows x (i,f),(g,o) pairs.
__device__ __forceinline__ void gemm_span(const float* Asm, const float* Wsm,
                                          int tj, int tb, int k0, int k1,
                                          u64 acc[2][2]) {
    const float* A0 = Asm + (tb * 2 + 0) * AS;
    const float* A1 = A0 + AS;

#pragma unroll 4
    for (int k = k0; k < k1; k += 4) {
        float4 a0 = *(const float4*)(A0 + k);
        float4 a1 = *(const float4*)(A1 + k);
        float a0v[4] = {a0.x, a0.y, a0.z, a0.w};
        float a1v[4] = {a1.x, a1.y, a1.z, a1.w};
#pragma unroll
        for (int kk = 0; kk < 4; kk++) {
            const u64* Wq = (const u64*)(Wsm + (k + kk) * WS) + tj * 2;
            u64 w01 = Wq[0];              // (w_i, w_f)
            u64 w23 = Wq[1];              // (w_g, w_o)
            u64 ad0 = pack2(a0v[kk], a0v[kk]);
            u64 ad1 = pack2(a1v[kk], a1v[kk]);
            acc[0][0] = ffma2(ad0, w01, acc[0][0]);
            acc[0][1] = ffma2(ad0, w23, acc[0][1]);
            acc[1][0] = ffma2(ad1, w01, acc[1][0]);
            acc[1][1] = ffma2(ad1, w23, acc[1][1]);
        }
    }
}

// PRE phase: stage x_t tile (32 x 64), init bias, x-part GEMM (k<64).
__device__ __forceinline__ void cell_pre(const float* __restrict__ src,
                                         int rowStride, int b0,
                                         const float* Wsm, float* Asm,
                                         const float* bsum, u64 acc[2][2]) {
    const int tid = threadIdx.x;
#pragma unroll
    for (int it = 0; it < 2; it++) {              // 32 rows x 16 float4
        int idx = tid + it * NTHR;
        int row = idx >> 4;
        int slot = idx & 15;
        float4 v = __ldcg((const float4*)(src + (size_t)(b0 + row) * rowStride) + slot);
        *(float4*)(Asm + row * AS + slot * 4) = v;
    }
    __syncthreads();

    const int tj = tid & 15;
    const int tb = tid >> 4;
    {
        float4 bv = *(const float4*)(bsum + tj * 4);
        u64 b01 = pack2(bv.x, bv.y);
        u64 b23 = pack2(bv.z, bv.w);
        acc[0][0] = b01; acc[0][1] = b23;
        acc[1][0] = b01; acc[1][1] = b23;
    }
    gemm_span(Asm, Wsm, tj, tb, 0, IN, acc);
}

// H phase: stage h tile (32 x 256) from hsrc, h-part GEMM, pointwise -> hdst.
__device__ __forceinline__ void cell_h(int d, int b0, int j0,
                                       const float* __restrict__ hsrc,
                                       float* __restrict__ hdst,
                                       const float* Wsm, float* Asm,
                                       u64 acc[2][2], float c_reg[2]) {
    const int tid = threadIdx.x;
#pragma unroll
    for (int it = 0; it < 8; it += 4) {           // 32 rows x 64 float4, MLP=4
        float4 v[4];
#pragma unroll
        for (int u = 0; u < 4; u++) {
            int idx = tid + (it + u) * NTHR;
            int row = idx >> 6;
            int slot = idx & 63;
            v[u] = __ldcg((const float4*)(hsrc + (size_t)((d << 7) + b0 + row) * HID) + slot);
        }
#pragma unroll
        for (int u = 0; u < 4; u++) {
            int idx = tid + (it + u) * NTHR;
            int row = idx >> 6;
            int slot = idx & 63;
            *(float4*)(Asm + row * AS + IN + slot * 4) = v[u];
        }
    }
    __syncthreads();

    const int tj = tid & 15;
    const int tb = tid >> 4;
    gemm_span(Asm, Wsm, tj, tb, IN, KTOT, acc);

    int j = j0 + tj;
#pragma unroll
    for (int bi = 0; bi < 2; bi++) {
        int b = b0 + tb * 2 + bi;
        float gi, gf, gg, go;
        unpack2(gi, gf, acc[bi][0]);
        unpack2(gg, go, acc[bi][1]);
        float cn = fsig(gf) * c_reg[bi] + fsig(gi) * ftanh(gg);
        float hn = fsig(go) * ftanh(cn);
        c_reg[bi] = cn;
        hdst[(size_t)((d << 7) + b) * HID + j] = hn;
    }
}

__global__ void __launch_bounds__(NTHR, 1)
lstm_s2s_kernel(const float* __restrict__ x,
                const float* __restrict__ eWih, const float* __restrict__ eWhh,
                const float* __restrict__ ebih, const float* __restrict__ ebhh,
                const float* __restrict__ dWih, const float* __restrict__ dWhh,
                const float* __restrict__ dbih, const float* __restrict__ dbhh,
                const float* __restrict__ linW, const float* __restrict__ linb,
                float* __restrict__ out) {
    extern __shared__ float smem[];
    float* Wsm  = smem;                      // [320][68]
    float* Asm  = Wsm + KTOT * WS;           // [32][328]
    float* bsum = Asm + 32 * AS;             // [64]
    float* red  = bsum + 64;                 // [256] projection scratch

    const int ct = blockIdx.x;
    const int d = ct >> 6;
    const int rem = ct & 63;
    const int b0 = (rem >> 4) * 32;
    const int j0 = (rem & 15) * 16;
    const int gbase = ct & ~15;              // 16 CTAs sharing (dir, b-tile)
    const int tid = threadIdx.x;

    float c_reg[2] = {0.f, 0.f};
    u64 acc[2][2];
    int hr = 0;                              // current valid h lives in buf hr&1

    // zero this CTA's h slice in buffer 0 (fresh state every replay)
    for (int idx = tid; idx < 32 * 16; idx += NTHR) {
        int bb = idx >> 4, jj = idx & 15;
        g_h[0][(size_t)((d << 7) + b0 + bb) * HID + j0 + jj] = 0.f;
    }
    release(1);
    int round = 1;

    load_phase_weights(Wsm, bsum, eWih, eWhh, ebih, ebhh, d, j0);

    // ===== encoder =====
    for (int r = 0; r < SEQLEN; r++) {
        int t = (d == 0) ? r : (SEQLEN - 1 - r);
        cell_pre(x + t * IN, SEQLEN * IN, b0, Wsm, Asm, bsum, acc);
        waitf(gbase, 16, round);
        cell_h(d, b0, j0, g_h[hr & 1], g_h[(hr + 1) & 1], Wsm, Asm, acc, c_reg);
        hr++;
        release(round + 1); round++;
    }

    // ===== switch to decoder weights =====
    load_phase_weights(Wsm, bsum, dWih, dWhh, dbih, dbhh, d, j0);

    // ===== decoder: 24 autoregressive iterations =====
    for (int t = 0; t < PRED; t++) {
        int L = (t == 0) ? 1 : t;
        for (int s = 0; s < L; s++) {
            const float* src;
            int stride;
            if (t == 0) {
                src = x + (SEQLEN - 1) * IN;          // x[:, -1, :]
                stride = SEQLEN * IN;
            } else {
                int yi = (d == 0) ? s : (L - 1 - s);
                src = g_y + (size_t)yi * BATCH * IN;
                stride = IN;
            }
            cell_pre(src, stride, b0, Wsm, Asm, bsum, acc);
            waitf(gbase, 16, round);
            cell_h(d, b0, j0, g_h[hr & 1], g_h[(hr + 1) & 1], Wsm, Asm, acc, c_reg);
            hr++;
            release(round + 1); round++;
        }

        // ---- projection: y_t = concat(hF, hB) @ linW^T + linb  (CTAs 0..63)
        if (ct < 64) {
            // wait only on the 32 producers (both dirs) of this b-tile
            if (tid < 32) {
                int base = (ct >> 4) * 16;
                int idx = base + (tid & 15) + ((tid & 16) ? 64 : 0);
                const int* p = &g_flags[idx];
                while (ld_acq(p) < round) { }
            }
            __syncthreads();

            const float* hb = g_h[hr & 1];
            int bsel = tid >> 7;              // 0..1
            int half = (tid >> 6) & 1;        // 0 = fwd h, 1 = bwd h
            int col  = tid & 63;
            int b = (ct << 1) + bsel;
            const float4* w4 = (const float4*)(linW + col * (2 * HID)) + half * (HID / 4);
            const float4* hv = (const float4*)(hb + (size_t)(half * BATCH + b) * HID);
            float s = 0.f;
#pragma unroll 8
            for (int q = 0; q < HID / 4; q++) {
                float4 f = __ldcg(hv + q);
                float4 w = __ldg(w4 + q);
                s += f.x * w.x + f.y * w.y + f.z * w.z + f.w * w.w;
            }
            red[tid] = s;
            __syncthreads();
            if (half == 0) {
                float rv = red[tid] + red[tid + 64] + linb[col];
                g_y[((size_t)t * BATCH + b) * IN + col] = rv;
                out[((size_t)b * PRED + t) * IN + col] = rv;
            }
        }
        release(round + 1); round++;
        // g_y rows for this CTA's b-tile come from projection CTAs [b0/2, b0/2+16)
        waitf(b0 >> 1, 16, round);
    }
}

extern "C" void kernel_launch(void* const* d_in, const int* in_sizes, int n_in,
                              void* d_out, int out_size) {
    const float* x    = (const float*)d_in[0];
    const float* eWih = (const float*)d_in[1];
    const float* eWhh = (const float*)d_in[2];
    const float* ebih = (const float*)d_in[3];
    const float* ebhh = (const float*)d_in[4];
    const float* dWih = (const float*)d_in[5];
    const float* dWhh = (const float*)d_in[6];
    const float* dbih = (const float*)d_in[7];
    const float* dbhh = (const float*)d_in[8];
    const float* linW = (const float*)d_in[9];
    const float* linb = (const float*)d_in[10];
    float* out = (float*)d_out;

    void* flagsPtr = nullptr;
    cudaGetSymbolAddress(&flagsPtr, g_flags);
    cudaMemsetAsync(flagsPtr, 0, sizeof(int) * NBLK, 0);

    cudaFuncSetAttribute(lstm_s2s_kernel,
                         cudaFuncAttributeMaxDynamicSharedMemorySize, SMEM_BYTES);

    lstm_s2s_kernel<<<NBLK, NTHR, SMEM_BYTES>>>(
        x, eWih, eWhh, ebih, ebhh, dWih, dWhh, dbih, dbhh, linW, linb, out);
}